// round 3
// baseline (speedup 1.0000x reference)
#include <cuda_runtime.h>
#include <stdint.h>

#define NMAX 100000

// Scratch (device globals — no allocation allowed)
__device__ float d_G[NMAX * 64];   // W_f @ f[n] + W_p @ node[n]
__device__ float d_P[NMAX * 64];   // W_p @ node[n]
__device__ float d_sum[64];
__device__ float d_sumsq[64];
__device__ float d_scale[64];
__device__ float d_bias[64];
__device__ int   d_is64;

// ---------------------------------------------------------------------------
// Detect whether the edges array is int64 or int32.
// int64 layout: [s0_lo, s0_hi, d0_lo, d0_hi, ...] — high words (odd int32
// indices) are 0 since all indices < 2^31. int32 layout puts random dst
// values at odd indices (P(all 8 zero) ~ 1e-40).
__global__ void k_detect(const int* __restrict__ e32) {
    int bad = 0;
#pragma unroll
    for (int i = 1; i < 16; i += 2) bad |= e32[i];
    d_is64 = (bad == 0) ? 1 : 0;
}

// Zero output (poisoned 0xAA) and the stat accumulators (graph is replayed!)
__global__ void k_zero(float* __restrict__ out, int out_size) {
    int n4 = out_size >> 2;
    int i = blockIdx.x * blockDim.x + threadIdx.x;
    if (i < n4) ((float4*)out)[i] = make_float4(0.f, 0.f, 0.f, 0.f);
    if (blockIdx.x == 0) {
        if (threadIdx.x < 64) { d_sum[threadIdx.x] = 0.f; d_sumsq[threadIdx.x] = 0.f; }
        if (threadIdx.x == 0)
            for (int t = n4 << 2; t < out_size; t++) out[t] = 0.f;
    }
}

// ---------------------------------------------------------------------------
// Per-node precompute: G[n][j], P[n][j]. thread = (node-slot, channel j),
// W row j (67 floats) lives in registers; f[n] read as broadcast float4 LDGs.
__global__ void k_pre(const float* __restrict__ nodep,
                      const float* __restrict__ feat,
                      const float* __restrict__ W, int Nn) {
    const int j    = threadIdx.x & 63;
    const int slot = threadIdx.x >> 6;
    const int npb  = blockDim.x >> 6;
    float w[64];
#pragma unroll
    for (int i = 0; i < 64; i++) w[i] = __ldg(&W[j * 67 + i]);
    const float wp0 = __ldg(&W[j * 67 + 64]);
    const float wp1 = __ldg(&W[j * 67 + 65]);
    const float wp2 = __ldg(&W[j * 67 + 66]);
    for (int n = blockIdx.x * npb + slot; n < Nn; n += gridDim.x * npb) {
        const float4* f4 = (const float4*)(feat + (size_t)n * 64);
        float acc = 0.f;
#pragma unroll
        for (int i4 = 0; i4 < 16; i4++) {
            float4 f = __ldg(&f4[i4]);
            acc = fmaf(f.x, w[4 * i4 + 0], acc);
            acc = fmaf(f.y, w[4 * i4 + 1], acc);
            acc = fmaf(f.z, w[4 * i4 + 2], acc);
            acc = fmaf(f.w, w[4 * i4 + 3], acc);
        }
        float p = wp0 * __ldg(&nodep[3 * n])
                + wp1 * __ldg(&nodep[3 * n + 1])
                + wp2 * __ldg(&nodep[3 * n + 2]);
        d_G[(size_t)n * 64 + j] = acc + p;
        d_P[(size_t)n * 64 + j] = p;
    }
}

// ---------------------------------------------------------------------------
// Pass 1: per-channel sum / sumsq of h over all edges.
// 16 lanes = 1 node; lane k preloads edge (n + k*Nn); lane cg owns channels
// 4cg..4cg+3 (float4). h = G[dst] - P[src]; P[n] cached when src==n.
__global__ void k_stats(const void* __restrict__ edges, int Nn, long long Ne) {
    __shared__ float s_sum[64];
    __shared__ float s_sq[64];
    if (threadIdx.x < 64) { s_sum[threadIdx.x] = 0.f; s_sq[threadIdx.x] = 0.f; }
    __syncthreads();
    const int lane = threadIdx.x & 31;
    const int cg   = lane & 15;
    const int half = lane & 16;
    const unsigned hm = 0xFFFFu << half;   // the two 16-lane halves can diverge
    const int is64 = d_is64;
    int gid     = (blockIdx.x * blockDim.x + threadIdx.x) >> 4;
    int gstride = (gridDim.x * blockDim.x) >> 4;
    float4 sum = make_float4(0.f, 0.f, 0.f, 0.f);
    float4 sq  = make_float4(0.f, 0.f, 0.f, 0.f);
    for (int n = gid; n < Nn; n += gstride) {
        long long e = (long long)n + (long long)cg * Nn;
        int es = 0, ed = 0;
        if (e < Ne) {
            if (is64) { longlong2 t = __ldg((const longlong2*)edges + e); es = (int)t.x; ed = (int)t.y; }
            else      { int2      t = __ldg((const int2*)edges + e);      es = t.x;      ed = t.y; }
        }
        float4 pn = __ldg((const float4*)(d_P + (size_t)n * 64 + cg * 4));
        int kmax = (int)((Ne - n + Nn - 1) / Nn);
        kmax = kmax > 16 ? 16 : kmax;
#pragma unroll
        for (int k = 0; k < 16; k++) {
            if (k >= kmax) break;
            int sk = __shfl_sync(hm, es, half + k);
            int dk = __shfl_sync(hm, ed, half + k);
            float4 g = __ldg((const float4*)(d_G + (size_t)dk * 64 + cg * 4));
            float4 p = pn;
            if (sk != n) p = __ldg((const float4*)(d_P + (size_t)sk * 64 + cg * 4));
            float dx = g.x - p.x, dy = g.y - p.y, dz = g.z - p.z, dw = g.w - p.w;
            sum.x += dx; sum.y += dy; sum.z += dz; sum.w += dw;
            sq.x = fmaf(dx, dx, sq.x); sq.y = fmaf(dy, dy, sq.y);
            sq.z = fmaf(dz, dz, sq.z); sq.w = fmaf(dw, dw, sq.w);
        }
    }
    __syncwarp();
#define RED16(v) v += __shfl_xor_sync(0xFFFFFFFFu, v, 16)
    RED16(sum.x); RED16(sum.y); RED16(sum.z); RED16(sum.w);
    RED16(sq.x);  RED16(sq.y);  RED16(sq.z);  RED16(sq.w);
    if (half == 0) {
        atomicAdd(&s_sum[4 * cg + 0], sum.x);
        atomicAdd(&s_sum[4 * cg + 1], sum.y);
        atomicAdd(&s_sum[4 * cg + 2], sum.z);
        atomicAdd(&s_sum[4 * cg + 3], sum.w);
        atomicAdd(&s_sq[4 * cg + 0], sq.x);
        atomicAdd(&s_sq[4 * cg + 1], sq.y);
        atomicAdd(&s_sq[4 * cg + 2], sq.z);
        atomicAdd(&s_sq[4 * cg + 3], sq.w);
    }
    __syncthreads();
    if (threadIdx.x < 64)       atomicAdd(&d_sum[threadIdx.x], s_sum[threadIdx.x]);
    else if (threadIdx.x < 128) atomicAdd(&d_sumsq[threadIdx.x - 64], s_sq[threadIdx.x - 64]);
}

__global__ void k_fin(const float* __restrict__ gamma,
                      const float* __restrict__ beta, float invNe) {
    int j = threadIdx.x;
    float mean = d_sum[j] * invNe;
    float var  = d_sumsq[j] * invNe - mean * mean;
    var = var > 0.f ? var : 0.f;
    float s = __ldg(&gamma[j]) * rsqrtf(var + 1e-5f);
    d_scale[j] = s;
    d_bias[j]  = __ldg(&beta[j]) - mean * s;
}

// ---------------------------------------------------------------------------
// Pass 2: y = relu(h*scale + bias); scatter-max into out[src].
// Structured src (src == n) folds into a register max + one atomicMax per
// (node, channel); stray edges fall back to per-edge atomicMax (still correct).
// y >= 0 so unsigned-bit atomicMax == float max, with out zero-initialized.
__global__ void k_out(const void* __restrict__ edges, int Nn, long long Ne,
                      unsigned* __restrict__ out) {
    const int lane = threadIdx.x & 31;
    const int cg   = lane & 15;
    const int half = lane & 16;
    const unsigned hm = 0xFFFFu << half;
    const int is64 = d_is64;
    int gid     = (blockIdx.x * blockDim.x + threadIdx.x) >> 4;
    int gstride = (gridDim.x * blockDim.x) >> 4;
    const float4 sc = __ldg((const float4*)(d_scale + cg * 4));
    const float4 bs = __ldg((const float4*)(d_bias + cg * 4));
    for (int n = gid; n < Nn; n += gstride) {
        long long e = (long long)n + (long long)cg * Nn;
        int es = 0, ed = 0;
        if (e < Ne) {
            if (is64) { longlong2 t = __ldg((const longlong2*)edges + e); es = (int)t.x; ed = (int)t.y; }
            else      { int2      t = __ldg((const int2*)edges + e);      es = t.x;      ed = t.y; }
        }
        float4 pn = __ldg((const float4*)(d_P + (size_t)n * 64 + cg * 4));
        int kmax = (int)((Ne - n + Nn - 1) / Nn);
        kmax = kmax > 16 ? 16 : kmax;
        float4 vmax = make_float4(0.f, 0.f, 0.f, 0.f);
#pragma unroll
        for (int k = 0; k < 16; k++) {
            if (k >= kmax) break;
            int sk = __shfl_sync(hm, es, half + k);
            int dk = __shfl_sync(hm, ed, half + k);
            float4 g = __ldg((const float4*)(d_G + (size_t)dk * 64 + cg * 4));
            float4 p = pn;
            if (sk != n) p = __ldg((const float4*)(d_P + (size_t)sk * 64 + cg * 4));
            float4 y;
            y.x = fmaxf(fmaf(g.x - p.x, sc.x, bs.x), 0.f);
            y.y = fmaxf(fmaf(g.y - p.y, sc.y, bs.y), 0.f);
            y.z = fmaxf(fmaf(g.z - p.z, sc.z, bs.z), 0.f);
            y.w = fmaxf(fmaf(g.w - p.w, sc.w, bs.w), 0.f);
            if (sk == n) {
                vmax.x = fmaxf(vmax.x, y.x);
                vmax.y = fmaxf(vmax.y, y.y);
                vmax.z = fmaxf(vmax.z, y.z);
                vmax.w = fmaxf(vmax.w, y.w);
            } else {
                unsigned* o = out + (size_t)sk * 64 + cg * 4;
                atomicMax(o + 0, __float_as_uint(y.x));
                atomicMax(o + 1, __float_as_uint(y.y));
                atomicMax(o + 2, __float_as_uint(y.z));
                atomicMax(o + 3, __float_as_uint(y.w));
            }
        }
        unsigned* o = out + (size_t)n * 64 + cg * 4;
        atomicMax(o + 0, __float_as_uint(vmax.x));
        atomicMax(o + 1, __float_as_uint(vmax.y));
        atomicMax(o + 2, __float_as_uint(vmax.z));
        atomicMax(o + 3, __float_as_uint(vmax.w));
    }
}

// ---------------------------------------------------------------------------
extern "C" void kernel_launch(void* const* d_in, const int* in_sizes, int n_in,
                              void* d_out, int out_size) {
    const float* nodep = (const float*)d_in[0];  // (Nn, 3)
    const float* feat  = (const float*)d_in[1];  // (Nn, 64)
    const float* W     = (const float*)d_in[2];  // (64, 67)
    const float* gamma = (const float*)d_in[3];  // (64,)
    const float* beta  = (const float*)d_in[4];  // (64,)
    const void*  edges = d_in[5];                // (Ne, 2) int32 or int64

    int       Nn = in_sizes[0] / 3;
    long long Ne = (long long)in_sizes[5] / 2;
    float*    out = (float*)d_out;

    k_detect<<<1, 1>>>((const int*)edges);
    k_zero<<<(out_size / 4 + 255) / 256, 256>>>(out, out_size);
    k_pre<<<592, 256>>>(nodep, feat, W, Nn);
    k_stats<<<1184, 256>>>(edges, Nn, Ne);
    k_fin<<<1, 64>>>(gamma, beta, 1.0f / (float)Ne);
    k_out<<<1184, 256>>>(edges, Nn, Ne, (unsigned*)out);
}

// round 7
// speedup vs baseline: 1.0756x; 1.0756x over previous
#include <cuda_runtime.h>
#include <stdint.h>

#define NMAX 100000

// Scratch (device globals — no allocation allowed)
__device__ float    d_G[NMAX * 64];   // W_f @ f[n] + W_p @ node[n]
__device__ float    d_P[NMAX * 64];   // W_p @ node[n]
__device__ unsigned d_maxk[NMAX * 64];
__device__ unsigned d_mink[NMAX * 64];
__device__ float    d_sum[64];
__device__ float    d_sumsq[64];
__device__ float    d_scale[64];
__device__ float    d_bias[64];
__device__ int      d_is64;

// Order-preserving float<->uint key (works for atomicMax/atomicMin)
__device__ __forceinline__ unsigned enc(float f) {
    unsigned u = __float_as_uint(f);
    return (u & 0x80000000u) ? ~u : (u | 0x80000000u);
}
__device__ __forceinline__ float dec(unsigned k) {
    return __uint_as_float((k & 0x80000000u) ? (k ^ 0x80000000u) : ~k);
}

// ---------------------------------------------------------------------------
// int64 vs int32 edge detection: int64 high words (odd int32 slots) of
// indices < 2^31 are all zero; int32 layout has random dst there.
__global__ void k_detect(const int* __restrict__ e32) {
    int bad = 0;
#pragma unroll
    for (int i = 1; i < 16; i += 2) bad |= e32[i];
    d_is64 = (bad == 0) ? 1 : 0;
}

// Reset per-replay state: minmax keys + stat accumulators. (out is fully
// overwritten by k_outfin, so no output zeroing needed.)
__global__ void k_init(int n4) {   // n4 = NMAX*64/4
    int i = blockIdx.x * blockDim.x + threadIdx.x;
    if (i < n4) {
        ((uint4*)d_maxk)[i] = make_uint4(0u, 0u, 0u, 0u);
        ((uint4*)d_mink)[i] = make_uint4(~0u, ~0u, ~0u, ~0u);
    }
    if (blockIdx.x == 0 && threadIdx.x < 64) {
        d_sum[threadIdx.x] = 0.f; d_sumsq[threadIdx.x] = 0.f;
    }
}

// ---------------------------------------------------------------------------
// Per-node precompute: G[n][j] = W_f@f[n] + W_p@node[n], P[n][j] = W_p@node[n]
__global__ void k_pre(const float* __restrict__ nodep,
                      const float* __restrict__ feat,
                      const float* __restrict__ W, int Nn) {
    const int j    = threadIdx.x & 63;
    const int slot = threadIdx.x >> 6;
    const int npb  = blockDim.x >> 6;
    float w[64];
#pragma unroll
    for (int i = 0; i < 64; i++) w[i] = __ldg(&W[j * 67 + i]);
    const float wp0 = __ldg(&W[j * 67 + 64]);
    const float wp1 = __ldg(&W[j * 67 + 65]);
    const float wp2 = __ldg(&W[j * 67 + 66]);
    for (int n = blockIdx.x * npb + slot; n < Nn; n += gridDim.x * npb) {
        const float4* f4 = (const float4*)(feat + (size_t)n * 64);
        float acc = 0.f;
#pragma unroll
        for (int i4 = 0; i4 < 16; i4++) {
            float4 f = __ldg(&f4[i4]);
            acc = fmaf(f.x, w[4 * i4 + 0], acc);
            acc = fmaf(f.y, w[4 * i4 + 1], acc);
            acc = fmaf(f.z, w[4 * i4 + 2], acc);
            acc = fmaf(f.w, w[4 * i4 + 3], acc);
        }
        float p = wp0 * __ldg(&nodep[3 * n])
                + wp1 * __ldg(&nodep[3 * n + 1])
                + wp2 * __ldg(&nodep[3 * n + 2]);
        d_G[(size_t)n * 64 + j] = acc + p;
        d_P[(size_t)n * 64 + j] = p;
    }
}

// ---------------------------------------------------------------------------
// SINGLE fused edge pass: per-channel sum/sumsq (LayerNorm stats) AND
// per-(node,channel) min/max of raw h = G[dst] - P[src].
// 16 lanes = 1 node; lane k preloads edge (n + k*Nn); lane cg owns channels
// 4cg..4cg+3. Structured edges (src==n) fold into register extremes with one
// atomic per node*channel; strays fall back to direct atomics (correct always).
__global__ void __launch_bounds__(256)
k_edge(const void* __restrict__ edges, int Nn, long long Ne) {
    __shared__ float s_sum[64];
    __shared__ float s_sq[64];
    if (threadIdx.x < 64) { s_sum[threadIdx.x] = 0.f; s_sq[threadIdx.x] = 0.f; }
    __syncthreads();
    const int lane = threadIdx.x & 31;
    const int cg   = lane & 15;
    const int half = lane & 16;
    const unsigned hm = 0xFFFFu << half;
    const int is64 = d_is64;
    int gid     = (blockIdx.x * blockDim.x + threadIdx.x) >> 4;
    int gstride = (gridDim.x * blockDim.x) >> 4;
    const float INF = __int_as_float(0x7f800000);
    float4 sum = make_float4(0.f, 0.f, 0.f, 0.f);
    float4 sq  = make_float4(0.f, 0.f, 0.f, 0.f);
    for (int n = gid; n < Nn; n += gstride) {
        long long e = (long long)n + (long long)cg * Nn;
        int es = 0, ed = 0;
        if (e < Ne) {
            if (is64) { longlong2 t = __ldg((const longlong2*)edges + e); es = (int)t.x; ed = (int)t.y; }
            else      { int2      t = __ldg((const int2*)edges + e);      es = t.x;      ed = t.y; }
        }
        float4 pn = __ldg((const float4*)(d_P + (size_t)n * 64 + cg * 4));
        int kmax = (int)((Ne - n + Nn - 1) / Nn);
        kmax = kmax > 16 ? 16 : kmax;
        float4 hmx = make_float4(-INF, -INF, -INF, -INF);
        float4 hmn = make_float4( INF,  INF,  INF,  INF);
#pragma unroll
        for (int k = 0; k < 16; k++) {
            if (k >= kmax) break;
            int sk = __shfl_sync(hm, es, half + k);
            int dk = __shfl_sync(hm, ed, half + k);
            float4 g = __ldg((const float4*)(d_G + (size_t)dk * 64 + cg * 4));
            float4 p = pn;
            if (sk != n) p = __ldg((const float4*)(d_P + (size_t)sk * 64 + cg * 4));
            float dx = g.x - p.x, dy = g.y - p.y, dz = g.z - p.z, dw = g.w - p.w;
            sum.x += dx; sum.y += dy; sum.z += dz; sum.w += dw;
            sq.x = fmaf(dx, dx, sq.x); sq.y = fmaf(dy, dy, sq.y);
            sq.z = fmaf(dz, dz, sq.z); sq.w = fmaf(dw, dw, sq.w);
            if (sk == n) {
                hmx.x = fmaxf(hmx.x, dx); hmx.y = fmaxf(hmx.y, dy);
                hmx.z = fmaxf(hmx.z, dz); hmx.w = fmaxf(hmx.w, dw);
                hmn.x = fminf(hmn.x, dx); hmn.y = fminf(hmn.y, dy);
                hmn.z = fminf(hmn.z, dz); hmn.w = fminf(hmn.w, dw);
            } else {
                unsigned* mo = d_maxk + (size_t)sk * 64 + cg * 4;
                unsigned* no = d_mink + (size_t)sk * 64 + cg * 4;
                atomicMax(mo + 0, enc(dx)); atomicMin(no + 0, enc(dx));
                atomicMax(mo + 1, enc(dy)); atomicMin(no + 1, enc(dy));
                atomicMax(mo + 2, enc(dz)); atomicMin(no + 2, enc(dz));
                atomicMax(mo + 3, enc(dw)); atomicMin(no + 3, enc(dw));
            }
        }
        unsigned* mo = d_maxk + (size_t)n * 64 + cg * 4;
        unsigned* no = d_mink + (size_t)n * 64 + cg * 4;
        atomicMax(mo + 0, enc(hmx.x)); atomicMin(no + 0, enc(hmn.x));
        atomicMax(mo + 1, enc(hmx.y)); atomicMin(no + 1, enc(hmn.y));
        atomicMax(mo + 2, enc(hmx.z)); atomicMin(no + 2, enc(hmn.z));
        atomicMax(mo + 3, enc(hmx.w)); atomicMin(no + 3, enc(hmn.w));
    }
    __syncwarp();
#define RED16(v) v += __shfl_xor_sync(0xFFFFFFFFu, v, 16)
    RED16(sum.x); RED16(sum.y); RED16(sum.z); RED16(sum.w);
    RED16(sq.x);  RED16(sq.y);  RED16(sq.z);  RED16(sq.w);
    if (half == 0) {
        atomicAdd(&s_sum[4 * cg + 0], sum.x); atomicAdd(&s_sum[4 * cg + 1], sum.y);
        atomicAdd(&s_sum[4 * cg + 2], sum.z); atomicAdd(&s_sum[4 * cg + 3], sum.w);
        atomicAdd(&s_sq[4 * cg + 0], sq.x);   atomicAdd(&s_sq[4 * cg + 1], sq.y);
        atomicAdd(&s_sq[4 * cg + 2], sq.z);   atomicAdd(&s_sq[4 * cg + 3], sq.w);
    }
    __syncthreads();
    if (threadIdx.x < 64)       atomicAdd(&d_sum[threadIdx.x], s_sum[threadIdx.x]);
    else if (threadIdx.x < 128) atomicAdd(&d_sumsq[threadIdx.x - 64], s_sq[threadIdx.x - 64]);
}

__global__ void k_fin(const float* __restrict__ gamma,
                      const float* __restrict__ beta, float invNe) {
    int j = threadIdx.x;
    float mean = d_sum[j] * invNe;
    float var  = d_sumsq[j] * invNe - mean * mean;
    var = var > 0.f ? var : 0.f;
    float s = __ldg(&gamma[j]) * rsqrtf(var + 1e-5f);
    d_scale[j] = s;
    d_bias[j]  = __ldg(&beta[j]) - mean * s;
}

// ---------------------------------------------------------------------------
// Finalize: y(n,c) = relu(s_c>0 ? maxh*s+b : s_c<0 ? minh*s+b : b).
// Monotone affine + relu: extreme of y == y(extreme of h). Untouched keys
// decode to NaN/∓inf, which fmaxf(.,0) collapses to 0 (zero-edge nodes).
__global__ void k_outfin(float* __restrict__ out, int Nn) {
    int t = blockIdx.x * blockDim.x + threadIdx.x;
    if (t >= Nn * 16) return;
    int cg = t & 15;
    float4 sc = *(const float4*)(d_scale + cg * 4);
    float4 bs = *(const float4*)(d_bias + cg * 4);
    uint4 mk = ((const uint4*)d_maxk)[t];
    uint4 nk = ((const uint4*)d_mink)[t];
    float4 y;
    float vx = (sc.x >= 0.f) ? dec(mk.x) : dec(nk.x);
    float vy = (sc.y >= 0.f) ? dec(mk.y) : dec(nk.y);
    float vz = (sc.z >= 0.f) ? dec(mk.z) : dec(nk.z);
    float vw = (sc.w >= 0.f) ? dec(mk.w) : dec(nk.w);
    y.x = fmaxf(fmaf(vx, sc.x, bs.x), 0.f);
    y.y = fmaxf(fmaf(vy, sc.y, bs.y), 0.f);
    y.z = fmaxf(fmaf(vz, sc.z, bs.z), 0.f);
    y.w = fmaxf(fmaf(vw, sc.w, bs.w), 0.f);
    ((float4*)out)[t] = y;
}

// ---------------------------------------------------------------------------
extern "C" void kernel_launch(void* const* d_in, const int* in_sizes, int n_in,
                              void* d_out, int out_size) {
    const float* nodep = (const float*)d_in[0];  // (Nn, 3)
    const float* feat  = (const float*)d_in[1];  // (Nn, 64)
    const float* W     = (const float*)d_in[2];  // (64, 67)
    const float* gamma = (const float*)d_in[3];  // (64,)
    const float* beta  = (const float*)d_in[4];  // (64,)
    const void*  edges = d_in[5];                // (Ne, 2) int32 or int64

    int       Nn = in_sizes[0] / 3;
    long long Ne = (long long)in_sizes[5] / 2;
    float*    out = (float*)d_out;

    int n4 = (Nn * 64) / 4;                      // uint4 count for key arrays
    k_detect<<<1, 1>>>((const int*)edges);
    k_init<<<(n4 + 255) / 256, 256>>>(n4);
    k_pre<<<592, 256>>>(nodep, feat, W, Nn);
    k_edge<<<1184, 256>>>(edges, Nn, Ne);
    k_fin<<<1, 64>>>(gamma, beta, 1.0f / (float)Ne);
    k_outfin<<<(Nn * 16 + 255) / 256, 256>>>(out, Nn);
}